// round 2
// baseline (speedup 1.0000x reference)
#include <cuda_runtime.h>
#include <stdint.h>

#define RES 512
#define CH 32
#define PLANE_ELEMS (RES * RES * CH)

// (H, W, C) transposed planes: each texel = 32 contiguous floats = one 128B line.
__device__ __align__(16) float g_TT[3][PLANE_ELEMS];

// ---------------------------------------------------------------------------
// Transpose (C, H, W) -> (H, W, C) via shared-memory 32x32 tile.
// grid = (RES, RES/32, 3), block = (32, 32)
// ---------------------------------------------------------------------------
__global__ __launch_bounds__(1024) void triplane_transpose_kernel(
    const float* __restrict__ t_xy,
    const float* __restrict__ t_yz,
    const float* __restrict__ t_zx)
{
    __shared__ float tile[32][33];

    const int y  = blockIdx.x;        // row in H
    const int x0 = blockIdx.y * 32;   // tile base in W
    const int p  = blockIdx.z;        // plane
    const int tx = threadIdx.x;
    const int ty = threadIdx.y;

    const float* src = (p == 0) ? t_xy : (p == 1) ? t_yz : t_zx;

    // read: channel = ty (fixed per row), x = x0 + tx -> coalesced 128B rows
    tile[ty][tx] = src[ty * (RES * RES) + y * RES + x0 + tx];
    __syncthreads();

    // write: x = x0 + ty, c = tx -> dst contiguous in tx (coalesced 128B rows)
    g_TT[p][(y * RES + x0 + ty) * CH + tx] = tile[tx][ty];
}

// ---------------------------------------------------------------------------
// Sampling kernel: 8 lanes per point, each lane owns 4 channels (float4).
// A warp covers 4 points; every corner fetch is one 128B-aligned cache line.
// ---------------------------------------------------------------------------
__global__ __launch_bounds__(256) void triplane_sample_kernel(
    const float* __restrict__ xyz,
    float* __restrict__ out,
    int npts)
{
    const int gtid = blockIdx.x * blockDim.x + threadIdx.x;
    const int pid  = gtid >> 3;       // point id
    const int c4   = gtid & 7;        // which float4 chunk of the 32 channels
    if (pid >= npts) return;

    const float cx = __ldg(xyz + pid * 3 + 0);
    const float cy = __ldg(xyz + pid * 3 + 1);
    const float cz = __ldg(xyz + pid * 3 + 2);

    // plane p: x-coord (W dim) = cA[p], y-coord (H dim) = cB[p]
    // f_xy: (X, Y)   f_yz: (Y, Z)   f_zx: (Z, X)
    const float cA[3] = {cx, cy, cz};
    const float cB[3] = {cy, cz, cx};

    float4 acc = make_float4(0.f, 0.f, 0.f, 0.f);

#pragma unroll
    for (int p = 0; p < 3; ++p) {
        // x = ((c + 1) * RES - 1) * 0.5 = 256*c + 255.5
        const float xf = fmaf(cA[p], 256.0f, 255.5f);
        const float yf = fmaf(cB[p], 256.0f, 255.5f);

        const float x0f = floorf(xf);
        const float y0f = floorf(yf);
        const float wx1 = xf - x0f;
        const float wy1 = yf - y0f;
        const float wx0 = 1.0f - wx1;
        const float wy0 = 1.0f - wy1;

        const int ix0 = (int)x0f;
        const int iy0 = (int)y0f;
        const int ix1 = ix0 + 1;
        const int iy1 = iy0 + 1;

        const bool vx0 = ((unsigned)ix0 < RES);
        const bool vx1 = ((unsigned)ix1 < RES);
        const bool vy0 = ((unsigned)iy0 < RES);
        const bool vy1 = ((unsigned)iy1 < RES);

        const float* base = g_TT[p] + c4 * 4;

        if (vy0 & vx0) {
            const float4 v = __ldg((const float4*)(base + (iy0 * RES + ix0) * CH));
            const float w = wy0 * wx0;
            acc.x = fmaf(w, v.x, acc.x); acc.y = fmaf(w, v.y, acc.y);
            acc.z = fmaf(w, v.z, acc.z); acc.w = fmaf(w, v.w, acc.w);
        }
        if (vy0 & vx1) {
            const float4 v = __ldg((const float4*)(base + (iy0 * RES + ix1) * CH));
            const float w = wy0 * wx1;
            acc.x = fmaf(w, v.x, acc.x); acc.y = fmaf(w, v.y, acc.y);
            acc.z = fmaf(w, v.z, acc.z); acc.w = fmaf(w, v.w, acc.w);
        }
        if (vy1 & vx0) {
            const float4 v = __ldg((const float4*)(base + (iy1 * RES + ix0) * CH));
            const float w = wy1 * wx0;
            acc.x = fmaf(w, v.x, acc.x); acc.y = fmaf(w, v.y, acc.y);
            acc.z = fmaf(w, v.z, acc.z); acc.w = fmaf(w, v.w, acc.w);
        }
        if (vy1 & vx1) {
            const float4 v = __ldg((const float4*)(base + (iy1 * RES + ix1) * CH));
            const float w = wy1 * wx1;
            acc.x = fmaf(w, v.x, acc.x); acc.y = fmaf(w, v.y, acc.y);
            acc.z = fmaf(w, v.z, acc.z); acc.w = fmaf(w, v.w, acc.w);
        }
    }

    // contiguous 512B per warp
    ((float4*)out)[pid * 8 + c4] = acc;
}

// ---------------------------------------------------------------------------
// kernel_launch
// inputs (metadata order): xyz [N*3], T_xy, T_yz, T_zx [1*32*512*512] fp32
// output: [N*32] fp32
// ---------------------------------------------------------------------------
extern "C" void kernel_launch(void* const* d_in, const int* in_sizes, int n_in,
                              void* d_out, int out_size)
{
    const float* xyz  = (const float*)d_in[0];
    const float* t_xy = (const float*)d_in[1];
    const float* t_yz = (const float*)d_in[2];
    const float* t_zx = (const float*)d_in[3];
    float* out = (float*)d_out;

    const int npts = in_sizes[0] / 3;

    // 1) transpose planes to (H, W, C)
    dim3 tgrid(RES, RES / 32, 3);
    dim3 tblock(32, 32);
    triplane_transpose_kernel<<<tgrid, tblock>>>(t_xy, t_yz, t_zx);

    // 2) sample: 8 threads per point
    const long long total = (long long)npts * 8;
    const int block = 256;
    const int grid = (int)((total + block - 1) / block);
    triplane_sample_kernel<<<grid, block>>>(xyz, out, npts);
}

// round 3
// speedup vs baseline: 1.0006x; 1.0006x over previous
#include <cuda_runtime.h>
#include <stdint.h>

#define RES 512
#define CH 32
#define PLANE_ELEMS (RES * RES * CH)

// (H, W, C) transposed planes: each texel = 32 contiguous floats = one 128B line.
__device__ __align__(16) float g_TT[3][PLANE_ELEMS];

// ---------------------------------------------------------------------------
// Transpose (C, H, W) -> (H, W, C) via shared-memory 32x32 tile.
// grid = (RES, RES/32, 3), block = (32, 32)
// ---------------------------------------------------------------------------
__global__ __launch_bounds__(1024) void triplane_transpose_kernel(
    const float* __restrict__ t_xy,
    const float* __restrict__ t_yz,
    const float* __restrict__ t_zx)
{
    __shared__ float tile[32][33];

    const int y  = blockIdx.x;        // row in H
    const int x0 = blockIdx.y * 32;   // tile base in W
    const int p  = blockIdx.z;        // plane
    const int tx = threadIdx.x;
    const int ty = threadIdx.y;

    const float* src = (p == 0) ? t_xy : (p == 1) ? t_yz : t_zx;

    // read: channel = ty (fixed per row), x = x0 + tx -> coalesced 128B rows
    tile[ty][tx] = src[ty * (RES * RES) + y * RES + x0 + tx];
    __syncthreads();

    // write: x = x0 + ty, c = tx -> dst contiguous in tx (coalesced 128B rows)
    g_TT[p][(y * RES + x0 + ty) * CH + tx] = tile[tx][ty];
}

// ---------------------------------------------------------------------------
// Sampling kernel: 8 lanes per point, each lane owns 4 channels (float4).
// A warp covers 4 points; every corner fetch is one 128B-aligned cache line.
// ---------------------------------------------------------------------------
__global__ __launch_bounds__(256) void triplane_sample_kernel(
    const float* __restrict__ xyz,
    float* __restrict__ out,
    int npts)
{
    const int gtid = blockIdx.x * blockDim.x + threadIdx.x;
    const int pid  = gtid >> 3;       // point id
    const int c4   = gtid & 7;        // which float4 chunk of the 32 channels
    if (pid >= npts) return;

    const float cx = __ldg(xyz + pid * 3 + 0);
    const float cy = __ldg(xyz + pid * 3 + 1);
    const float cz = __ldg(xyz + pid * 3 + 2);

    // plane p: x-coord (W dim) = cA[p], y-coord (H dim) = cB[p]
    // f_xy: (X, Y)   f_yz: (Y, Z)   f_zx: (Z, X)
    const float cA[3] = {cx, cy, cz};
    const float cB[3] = {cy, cz, cx};

    float4 acc = make_float4(0.f, 0.f, 0.f, 0.f);

#pragma unroll
    for (int p = 0; p < 3; ++p) {
        // x = ((c + 1) * RES - 1) * 0.5 = 256*c + 255.5
        const float xf = fmaf(cA[p], 256.0f, 255.5f);
        const float yf = fmaf(cB[p], 256.0f, 255.5f);

        const float x0f = floorf(xf);
        const float y0f = floorf(yf);
        const float wx1 = xf - x0f;
        const float wy1 = yf - y0f;
        const float wx0 = 1.0f - wx1;
        const float wy0 = 1.0f - wy1;

        const int ix0 = (int)x0f;
        const int iy0 = (int)y0f;
        const int ix1 = ix0 + 1;
        const int iy1 = iy0 + 1;

        const bool vx0 = ((unsigned)ix0 < RES);
        const bool vx1 = ((unsigned)ix1 < RES);
        const bool vy0 = ((unsigned)iy0 < RES);
        const bool vy1 = ((unsigned)iy1 < RES);

        const float* base = g_TT[p] + c4 * 4;

        if (vy0 & vx0) {
            const float4 v = __ldg((const float4*)(base + (iy0 * RES + ix0) * CH));
            const float w = wy0 * wx0;
            acc.x = fmaf(w, v.x, acc.x); acc.y = fmaf(w, v.y, acc.y);
            acc.z = fmaf(w, v.z, acc.z); acc.w = fmaf(w, v.w, acc.w);
        }
        if (vy0 & vx1) {
            const float4 v = __ldg((const float4*)(base + (iy0 * RES + ix1) * CH));
            const float w = wy0 * wx1;
            acc.x = fmaf(w, v.x, acc.x); acc.y = fmaf(w, v.y, acc.y);
            acc.z = fmaf(w, v.z, acc.z); acc.w = fmaf(w, v.w, acc.w);
        }
        if (vy1 & vx0) {
            const float4 v = __ldg((const float4*)(base + (iy1 * RES + ix0) * CH));
            const float w = wy1 * wx0;
            acc.x = fmaf(w, v.x, acc.x); acc.y = fmaf(w, v.y, acc.y);
            acc.z = fmaf(w, v.z, acc.z); acc.w = fmaf(w, v.w, acc.w);
        }
        if (vy1 & vx1) {
            const float4 v = __ldg((const float4*)(base + (iy1 * RES + ix1) * CH));
            const float w = wy1 * wx1;
            acc.x = fmaf(w, v.x, acc.x); acc.y = fmaf(w, v.y, acc.y);
            acc.z = fmaf(w, v.z, acc.z); acc.w = fmaf(w, v.w, acc.w);
        }
    }

    // contiguous 512B per warp
    ((float4*)out)[pid * 8 + c4] = acc;
}

// ---------------------------------------------------------------------------
// kernel_launch
// inputs (metadata order): xyz [N*3], T_xy, T_yz, T_zx [1*32*512*512] fp32
// output: [N*32] fp32
// ---------------------------------------------------------------------------
extern "C" void kernel_launch(void* const* d_in, const int* in_sizes, int n_in,
                              void* d_out, int out_size)
{
    const float* xyz  = (const float*)d_in[0];
    const float* t_xy = (const float*)d_in[1];
    const float* t_yz = (const float*)d_in[2];
    const float* t_zx = (const float*)d_in[3];
    float* out = (float*)d_out;

    const int npts = in_sizes[0] / 3;

    // 1) transpose planes to (H, W, C)
    dim3 tgrid(RES, RES / 32, 3);
    dim3 tblock(32, 32);
    triplane_transpose_kernel<<<tgrid, tblock>>>(t_xy, t_yz, t_zx);

    // 2) sample: 8 threads per point
    const long long total = (long long)npts * 8;
    const int block = 256;
    const int grid = (int)((total + block - 1) / block);
    triplane_sample_kernel<<<grid, block>>>(xyz, out, npts);
}

// round 4
// speedup vs baseline: 2.0129x; 2.0118x over previous
#include <cuda_runtime.h>
#include <cuda_fp16.h>
#include <stdint.h>

#define RES 512
#define CH 32
#define PLANE_ELEMS (RES * RES * CH)

// (H, W, C) transposed planes in fp16: each texel = 32 halves = 64 B.
__device__ __align__(16) __half g_TH[3][PLANE_ELEMS];

// ---------------------------------------------------------------------------
// Transpose (C, H, W) fp32 -> (H, W, C) fp16 via shared 32x32 tile.
// grid = (RES, RES/32, 3), block = (32, 8). Each thread loads 4 channels.
// ---------------------------------------------------------------------------
__global__ __launch_bounds__(256) void triplane_transpose_kernel(
    const float* __restrict__ t_xy,
    const float* __restrict__ t_yz,
    const float* __restrict__ t_zx)
{
    __shared__ float tile[32][33];   // [channel][x]

    const int y  = blockIdx.x;        // row in H
    const int x0 = blockIdx.y * 32;   // tile base in W
    const int p  = blockIdx.z;        // plane
    const int tx = threadIdx.x;       // 0..31 (x within tile)
    const int ty = threadIdx.y;       // 0..7

    const float* src = (p == 0) ? t_xy : (p == 1) ? t_yz : t_zx;
    const float* s = src + y * RES + x0 + tx;

    // 4 independent loads per thread (MLP=4), each row fully coalesced.
#pragma unroll
    for (int i = 0; i < 4; ++i) {
        const int c = ty + 8 * i;
        tile[c][tx] = s[c * (RES * RES)];
    }
    __syncthreads();

    // Write 32 texels x 16 half2 = 512 items with 256 threads (2 iterations).
    __half2* dst = (__half2*)(g_TH[p] + (y * RES + x0) * CH);
    const int tid = ty * 32 + tx;
#pragma unroll
    for (int it = 0; it < 2; ++it) {
        const int item = it * 256 + tid;
        const int xx = item >> 4;       // texel within tile (0..31)
        const int c2 = item & 15;       // half2 channel pair (0..15)
        dst[xx * (CH / 2) + c2] =
            __floats2half2_rn(tile[2 * c2][xx], tile[2 * c2 + 1][xx]);
    }
}

// ---------------------------------------------------------------------------
// Sampling kernel: 4 lanes per point, each lane owns 8 channels.
// Each corner fetch = one 16B LDG.128 from a 64B-aligned fp16 texel.
// ---------------------------------------------------------------------------
__global__ __launch_bounds__(256) void triplane_sample_kernel(
    const float* __restrict__ xyz,
    float* __restrict__ out,
    int npts)
{
    const int gtid = blockIdx.x * blockDim.x + threadIdx.x;
    const int pid  = gtid >> 2;       // point id
    const int q    = gtid & 3;        // which 8-channel chunk
    if (pid >= npts) return;

    const float cx = __ldg(xyz + pid * 3 + 0);
    const float cy = __ldg(xyz + pid * 3 + 1);
    const float cz = __ldg(xyz + pid * 3 + 2);

    // f_xy: (X, Y)   f_yz: (Y, Z)   f_zx: (Z, X)
    const float cA[3] = {cx, cy, cz};   // W coordinate
    const float cB[3] = {cy, cz, cx};   // H coordinate

    float2 acc[4];
#pragma unroll
    for (int j = 0; j < 4; ++j) acc[j] = make_float2(0.f, 0.f);

#pragma unroll
    for (int p = 0; p < 3; ++p) {
        // x = ((c + 1) * RES - 1) * 0.5 = 256*c + 255.5
        const float xf = fmaf(cA[p], 256.0f, 255.5f);
        const float yf = fmaf(cB[p], 256.0f, 255.5f);

        const float x0f = floorf(xf);
        const float y0f = floorf(yf);
        const float wx1 = xf - x0f;
        const float wy1 = yf - y0f;
        const float wx0 = 1.0f - wx1;
        const float wy0 = 1.0f - wy1;

        const int ix0 = (int)x0f;
        const int iy0 = (int)y0f;
        const int ix1 = ix0 + 1;
        const int iy1 = iy0 + 1;

        const bool vx0 = ((unsigned)ix0 < RES);
        const bool vx1 = ((unsigned)ix1 < RES);
        const bool vy0 = ((unsigned)iy0 < RES);
        const bool vy1 = ((unsigned)iy1 < RES);

        const __half* base = g_TH[p] + q * 8;   // this lane's 8 channels

#define CORNER(IY, IX, W)                                                     \
        {                                                                     \
            const uint4 v = __ldg((const uint4*)(base + ((IY) * RES + (IX)) * CH)); \
            const __half2* h = (const __half2*)&v;                            \
            const float w = (W);                                              \
            _Pragma("unroll")                                                 \
            for (int j = 0; j < 4; ++j) {                                     \
                const float2 f = __half22float2(h[j]);                        \
                acc[j].x = fmaf(w, f.x, acc[j].x);                            \
                acc[j].y = fmaf(w, f.y, acc[j].y);                            \
            }                                                                 \
        }

        if (vy0 & vx0) CORNER(iy0, ix0, wy0 * wx0);
        if (vy0 & vx1) CORNER(iy0, ix1, wy0 * wx1);
        if (vy1 & vx0) CORNER(iy1, ix0, wy1 * wx0);
        if (vy1 & vx1) CORNER(iy1, ix1, wy1 * wx1);
#undef CORNER
    }

    // 8 contiguous floats per lane -> two float4 stores, 1KB/warp contiguous.
    float4* o = (float4*)(out + pid * CH + q * 8);
    o[0] = make_float4(acc[0].x, acc[0].y, acc[1].x, acc[1].y);
    o[1] = make_float4(acc[2].x, acc[2].y, acc[3].x, acc[3].y);
}

// ---------------------------------------------------------------------------
// kernel_launch
// inputs (metadata order): xyz [N*3], T_xy, T_yz, T_zx [1*32*512*512] fp32
// output: [N*32] fp32
// ---------------------------------------------------------------------------
extern "C" void kernel_launch(void* const* d_in, const int* in_sizes, int n_in,
                              void* d_out, int out_size)
{
    const float* xyz  = (const float*)d_in[0];
    const float* t_xy = (const float*)d_in[1];
    const float* t_yz = (const float*)d_in[2];
    const float* t_zx = (const float*)d_in[3];
    float* out = (float*)d_out;

    const int npts = in_sizes[0] / 3;

    // 1) transpose + fp32->fp16 convert to (H, W, C)
    dim3 tgrid(RES, RES / 32, 3);
    dim3 tblock(32, 8);
    triplane_transpose_kernel<<<tgrid, tblock>>>(t_xy, t_yz, t_zx);

    // 2) sample: 4 threads per point
    const long long total = (long long)npts * 4;
    const int block = 256;
    const int grid = (int)((total + block - 1) / block);
    triplane_sample_kernel<<<grid, block>>>(xyz, out, npts);
}